// round 11
// baseline (speedup 1.0000x reference)
#include <cuda_runtime.h>
#include <cuda_bf16.h>
#include <cstdint>

// ============================================================================
// SelfAttention, single-pass tf32 mma.m16n8k8, cp.async 3-stage pipeline.
// R11 = R10 with the B-operand stage-offset bug fixed (reader now applies
// OFF_B; in R10 the B fragments were read from the A region -> rel_err ~1).
// Structure: 512 thr, CTA 128x128, warp 32x32, K-chunk 64, fused QKV,
// shuffle softmax. All operands pre-rounded to tf32 (cvt.rna).
// ============================================================================

constexpr int S = 2048, D = 1024, NB = 4;
constexpr long SD  = (long)S * D;
constexpr long SSZ = (long)S * S;
constexpr long NX = (long)NB * S * D;      // 8,388,608
constexpr long NW = (long)D * D;           // 1,048,576
constexpr long NP = (long)NB * S * S;      // 16,777,216

// float (tf32-rounded) scratch offsets
constexpr long OX  = 0;
constexpr long OWQ = NX, OWK = NX + NW, OWV = NX + 2 * NW;
constexpr long OQ  = NX + 3 * NW, OK_ = OQ + NX, OVT = OQ + 2 * NX;
constexpr long OP  = OQ + 3 * NX;
constexpr long NF  = OP + NP;

__device__ __align__(128) float g_f[NF];
__device__ float g_sc[NP];                 // fp32 scores

constexpr int STAGE = 64 * 1024;           // A 32KB | B 32KB (256 srows x 128B)
constexpr int OFF_B = 32768;
constexpr int NSTG  = 3;
constexpr int SMEM_DYN = NSTG * STAGE + 1024;

#define SWZ(o) ((o) ^ (((o) >> 3) & 0x70))

// ---------------------------------------------------------------- helpers
__device__ __forceinline__ uint32_t smem_u32(const void* p) {
    uint32_t a;
    asm("{ .reg .u64 t; cvta.to.shared.u64 t, %1; cvt.u32.u64 %0, t; }"
        : "=r"(a) : "l"(p));
    return a;
}
__device__ __forceinline__ void ldsm4(uint32_t* r, uint32_t addr) {
    asm volatile("ldmatrix.sync.aligned.m8n8.x4.shared.b16 {%0,%1,%2,%3}, [%4];"
                 : "=r"(r[0]), "=r"(r[1]), "=r"(r[2]), "=r"(r[3]) : "r"(addr));
}
__device__ __forceinline__ void mma_tf32(float* d, const uint32_t* a,
                                         const uint32_t* b) {
    asm volatile(
        "mma.sync.aligned.m16n8k8.row.col.f32.tf32.tf32.f32 "
        "{%0,%1,%2,%3}, {%4,%5,%6,%7}, {%8,%9}, {%0,%1,%2,%3};"
        : "+f"(d[0]), "+f"(d[1]), "+f"(d[2]), "+f"(d[3])
        : "r"(a[0]), "r"(a[1]), "r"(a[2]), "r"(a[3]), "r"(b[0]), "r"(b[1]));
}
__device__ __forceinline__ uint32_t to_tf32(float v) {
    uint32_t u;
    asm("cvt.rna.tf32.f32 %0, %1;" : "=r"(u) : "f"(v));
    return u;
}
#define CPA16(dst, src) \
    asm volatile("cp.async.cg.shared.global [%0], [%1], 16;" \
                 :: "r"(dst), "l"(src) : "memory")
#define CP_COMMIT() asm volatile("cp.async.commit_group;" ::: "memory")

// ---------------------------------------------------------------- converter
__global__ void __launch_bounds__(256)
conv_arr(const float* __restrict__ in, float* __restrict__ o, long n)
{
    long i = ((long)blockIdx.x * 256 + threadIdx.x) * 4;
    if (i >= n) return;
    float4 v = *reinterpret_cast<const float4*>(in + i);
    uint4 u = make_uint4(to_tf32(v.x), to_tf32(v.y), to_tf32(v.z), to_tf32(v.w));
    *reinterpret_cast<uint4*>(o + i) = u;
}

// ---------------------------------------------------------------- mainloop
// 512 thr, 16 warps (4m x 4n), warp 32x32, CTA 128x128, K-chunk 64 tf32.
// Stage: logical row r (64 tf32 = 256B) stored as srows 2r (k0-31) and
// 2r+1 (k32-63), each 128B swizzled. B identical at OFF_B.
__device__ __forceinline__ void gemm_mainloop(
    const float* __restrict__ gA, const float* __restrict__ gB,
    int lda, int ldb, int K, uint32_t abase, float* acc)
{
    const int tid = threadIdx.x, lane = tid & 31, wid = tid >> 5;

    // ---- cp.async loader: q=0..3: srow = (tid>>3)+64q, seg = tid&7 (16B)
    const int seg = tid & 7;
    const float* pA[4]; const float* pB[4];
    uint32_t aoff[4], boff[4];
#pragma unroll
    for (int q = 0; q < 4; q++) {
        const int srow = (tid >> 3) + 64 * q;
        const int r = srow >> 1, h = srow & 1;
        pA[q] = gA + (long)r * lda + h * 32 + seg * 4;
        pB[q] = gB + (long)r * ldb + h * 32 + seg * 4;
        const uint32_t so = SWZ((uint32_t)srow * 128 + seg * 16);
        aoff[q] = so; boff[q] = OFF_B + so;
    }

    // ---- fragment constants (warp 32x32 at (mw,nw))
    const int mw = (wid >> 2) * 32, nw = (wid & 3) * 32;
    const int m_local = (lane & 7) + ((lane >> 3) & 1) * 8;
    const int n_local = (lane & 7) + ((lane >> 4) & 1) * 8;
    const uint32_t a_cadd = (uint32_t)((lane >> 4) << 4);       // 0/16 bytes
    const uint32_t b_cadd = (uint32_t)(((lane >> 3) & 1) << 4); // 0/16 bytes
    uint32_t a_base[2][2], a_swz[2][2], b_base[2][2], b_swz[2][2];
#pragma unroll
    for (int i = 0; i < 2; i++)
#pragma unroll
        for (int h = 0; h < 2; h++) {
            const uint32_t sa = 2u * (mw + 16 * i + m_local) + h;
            a_base[i][h] = sa * 128; a_swz[i][h] = (sa & 7) << 4;
            const uint32_t sbr = 2u * (nw + 16 * i + n_local) + h;
            b_base[i][h] = OFF_B + sbr * 128;      // <-- R10 bug: OFF_B was missing
            b_swz[i][h] = (sbr & 7) << 4;
        }

    const int nch = K >> 6;

#define ISSUE(ch) do {                                                        \
        const uint32_t _sb = abase + (uint32_t)((ch) % NSTG) * STAGE;         \
        const long _k = (long)(ch) * 64;                                      \
        _Pragma("unroll")                                                     \
        for (int q = 0; q < 4; q++) {                                         \
            CPA16(_sb + aoff[q], pA[q] + _k);                                 \
            CPA16(_sb + boff[q], pB[q] + _k);                                 \
        }                                                                     \
        CP_COMMIT();                                                          \
    } while (0)

    ISSUE(0);
    ISSUE(1);

    for (int ch = 0; ch < nch; ch++) {
        if (ch + 1 < nch)
            asm volatile("cp.async.wait_group 1;" ::: "memory");
        else
            asm volatile("cp.async.wait_group 0;" ::: "memory");
        __syncthreads();
        if (ch + 2 < nch) ISSUE(ch + 2);

        const uint32_t sb = abase + (uint32_t)(ch % NSTG) * STAGE;
#pragma unroll
        for (int half = 0; half < 2; half++) {
#pragma unroll
            for (int ksc = 0; ksc < 4; ksc++) {
                const uint32_t col = (uint32_t)ksc * 32;
                uint32_t af[2][4], bf[2][4];
#pragma unroll
                for (int i = 0; i < 2; i++)
                    ldsm4(af[i], sb + a_base[i][half] +
                                 ((col + a_cadd) ^ a_swz[i][half]));
#pragma unroll
                for (int j = 0; j < 2; j++)
                    ldsm4(bf[j], sb + b_base[j][half] +
                                 ((col + b_cadd) ^ b_swz[j][half]));
#pragma unroll
                for (int i = 0; i < 2; i++)
#pragma unroll
                    for (int j = 0; j < 2; j++) {
                        mma_tf32(acc + (i * 4 + 2 * j) * 4,     af[i], &bf[j][0]);
                        mma_tf32(acc + (i * 4 + 2 * j + 1) * 4, af[i], &bf[j][2]);
                    }
            }
        }
    }
#undef ISSUE
}

// ---------------------------------------------------------------- fused QKV
// grid (D/128, NB*S/128, 3): z=0 Q, z=1 K (row-major tf32), z=2 VT
// (per-batch transposed tf32, ld = S, smem-staged).
__global__ void __launch_bounds__(512, 1)
mma_qkv(const float* __restrict__ bq, const float* __restrict__ bk,
        const float* __restrict__ bv)
{
    const int z = blockIdx.z;
    const long row0 = (long)blockIdx.y * 128, col0 = (long)blockIdx.x * 128;

    extern __shared__ char smem_raw[];
    const uint32_t rawb  = smem_u32(smem_raw);
    const uint32_t abase = (rawb + 1023) & ~1023u;
    char* smem = smem_raw + (abase - rawb);

    const float* W = &g_f[z == 0 ? OWQ : z == 1 ? OWK : OWV];
    const float* bias = z == 0 ? bq : z == 1 ? bk : bv;

    float acc[32];
#pragma unroll
    for (int i = 0; i < 32; i++) acc[i] = 0.f;

    gemm_mainloop(&g_f[OX] + row0 * D, W + col0 * D, D, D, D, abase, acc);

    const int tid = threadIdx.x, lane = tid & 31, wid = tid >> 5;
    const int mw = (wid >> 2) * 32, nw = (wid & 3) * 32;
    const int qr = lane >> 2, qc = lane & 3;

    if (z < 2) {
        float* C = &g_f[z == 0 ? OQ : OK_];
#pragma unroll
        for (int i = 0; i < 2; i++)
#pragma unroll
            for (int j = 0; j < 4; j++) {
                const float* d = acc + (i * 4 + j) * 4;
#pragma unroll
                for (int h = 0; h < 2; h++) {
                    const long r = row0 + mw + 16 * i + qr + 8 * h;
                    const long c = col0 + nw + 8 * j + 2 * qc;
                    uint2 u = make_uint2(to_tf32(d[2 * h] + bias[c]),
                                         to_tf32(d[2 * h + 1] + bias[c + 1]));
                    *reinterpret_cast<uint2*>(&C[r * D + c]) = u;
                }
            }
    } else {
        // VT: stage transposed tile in smem (pipeline dead), coalesced stores.
        const long b = row0 >> 11, rloc = row0 & (S - 1);
        float* C = &g_f[OVT] + b * SD;
        __syncthreads();
        float* sh = reinterpret_cast<float*>(smem);
#pragma unroll
        for (int i = 0; i < 2; i++)
#pragma unroll
            for (int j = 0; j < 4; j++) {
                const float* d = acc + (i * 4 + j) * 4;
#pragma unroll
                for (int h = 0; h < 2; h++) {
                    const int rl = mw + 16 * i + qr + 8 * h;
                    const int cl = nw + 8 * j + 2 * qc;
                    uint32_t u0 = to_tf32(d[2 * h] + bias[col0 + cl]);
                    uint32_t u1 = to_tf32(d[2 * h + 1] + bias[col0 + cl + 1]);
                    sh[cl * 132 + rl]       = __uint_as_float(u0);
                    sh[(cl + 1) * 132 + rl] = __uint_as_float(u1);
                }
            }
        __syncthreads();
        const int c = tid >> 2, sg = tid & 3;   // 128 cols x 4 segs of 32 floats
        const float* sr = sh + c * 132 + sg * 32;
        float* ds = C + (col0 + c) * (long)S + rloc + sg * 32;
#pragma unroll
        for (int q = 0; q < 8; q++)
            *reinterpret_cast<uint4*>(ds + q * 4) =
                *reinterpret_cast<const uint4*>(sr + q * 4);
    }
}

// ---------------------------------------------------------------- generic GEMM
// fp32 out: Cf[r*ldc + c] = scale * A@B^T. Batched by blockIdx.z.
__global__ void __launch_bounds__(512, 1)
mma_gemm(const float* __restrict__ A, const float* __restrict__ B,
         float* __restrict__ Cf, int K, int lda, int ldb, int ldc,
         long sA, long sB, long sC, float scale)
{
    const long zb = blockIdx.z;
    const long row0 = (long)blockIdx.y * 128, col0 = (long)blockIdx.x * 128;

    extern __shared__ char smem_raw[];
    const uint32_t rawb  = smem_u32(smem_raw);
    const uint32_t abase = (rawb + 1023) & ~1023u;

    float acc[32];
#pragma unroll
    for (int i = 0; i < 32; i++) acc[i] = 0.f;

    gemm_mainloop(A + sA * zb + row0 * (long)lda,
                  B + sB * zb + col0 * (long)ldb, lda, ldb, K, abase, acc);

    float* Cp = Cf + sC * zb;
    const int tid = threadIdx.x, lane = tid & 31, wid = tid >> 5;
    const int mw = (wid >> 2) * 32, nw = (wid & 3) * 32;
    const int qr = lane >> 2, qc = lane & 3;
#pragma unroll
    for (int i = 0; i < 2; i++)
#pragma unroll
        for (int j = 0; j < 4; j++) {
            const float* d = acc + (i * 4 + j) * 4;
#pragma unroll
            for (int h = 0; h < 2; h++) {
                const long r = row0 + mw + 16 * i + qr + 8 * h;
                const long c = col0 + nw + 8 * j + 2 * qc;
                *reinterpret_cast<float2*>(&Cp[r * (long)ldc + c]) =
                    make_float2(d[2 * h] * scale, d[2 * h + 1] * scale);
            }
        }
}

// ---------------------------------------------------------------- softmax
__global__ void __launch_bounds__(256)
softmax_rows(const float* __restrict__ sc, float* __restrict__ pt)
{
    const long ro = (long)blockIdx.x * 2048;
    const float* p = sc + ro;
    __shared__ float red[8];
    const int t = threadIdx.x, lane = t & 31, w = t >> 5;

    float v[8];
    float m = -3.4e38f;
#pragma unroll
    for (int i = 0; i < 8; i++) { v[i] = p[t + (i << 8)]; m = fmaxf(m, v[i]); }
#pragma unroll
    for (int o = 16; o > 0; o >>= 1)
        m = fmaxf(m, __shfl_xor_sync(0xffffffffu, m, o));
    if (lane == 0) red[w] = m;
    __syncthreads();
    m = red[lane & 7];
#pragma unroll
    for (int o = 4; o > 0; o >>= 1)
        m = fmaxf(m, __shfl_xor_sync(0xffffffffu, m, o));

    float sum = 0.f;
#pragma unroll
    for (int i = 0; i < 8; i++) { v[i] = __expf(v[i] - m); sum += v[i]; }
#pragma unroll
    for (int o = 16; o > 0; o >>= 1)
        sum += __shfl_xor_sync(0xffffffffu, sum, o);
    __syncthreads();
    if (lane == 0) red[w] = sum;
    __syncthreads();
    sum = red[lane & 7];
#pragma unroll
    for (int o = 4; o > 0; o >>= 1)
        sum += __shfl_xor_sync(0xffffffffu, sum, o);
    const float inv = 1.f / sum;

#pragma unroll
    for (int i = 0; i < 8; i++) {
        uint32_t u = to_tf32(v[i] * inv);
        pt[ro + t + (i << 8)] = __uint_as_float(u);
    }
}

// ---------------------------------------------------------------- launch
extern "C" void kernel_launch(void* const* d_in, const int* in_sizes, int n_in,
                              void* d_out, int out_size)
{
    const float* x  = (const float*)d_in[0];
    const float* Wq = (const float*)d_in[1];
    const float* bq = (const float*)d_in[2];
    const float* Wk = (const float*)d_in[3];
    const float* bk = (const float*)d_in[4];
    const float* Wv = (const float*)d_in[5];
    const float* bv = (const float*)d_in[6];
    float* out = (float*)d_out;

    float* gf; float* scp;
    cudaGetSymbolAddress((void**)&gf, g_f);
    cudaGetSymbolAddress((void**)&scp, g_sc);

    cudaFuncSetAttribute(mma_qkv, cudaFuncAttributeMaxDynamicSharedMemorySize,
                         SMEM_DYN);
    cudaFuncSetAttribute(mma_gemm, cudaFuncAttributeMaxDynamicSharedMemorySize,
                         SMEM_DYN);
    dim3 thr(512);

    // launches 1-4: tf32 rounding converters
    conv_arr<<<(int)(NX / 1024), 256>>>(x,  gf + OX,  NX);
    conv_arr<<<(int)(NW / 1024), 256>>>(Wq, gf + OWQ, NW);
    conv_arr<<<(int)(NW / 1024), 256>>>(Wk, gf + OWK, NW);
    conv_arr<<<(int)(NW / 1024), 256>>>(Wv, gf + OWV, NW);

    // launch 5: fused Q/K/VT projections
    dim3 g_qkv(D / 128, (NB * S) / 128, 3);
    mma_qkv<<<g_qkv, thr, SMEM_DYN>>>(bq, bk, bv);

    // launch 6 (ncu target): Sc = Q@K^T / 32 (fp32), batched
    dim3 g_sc(S / 128, S / 128, NB);
    mma_gemm<<<g_sc, thr, SMEM_DYN>>>(gf + OQ, gf + OK_,
                                      scp, D, D, D, S, SD, SD, SSZ, 0.03125f);

    // launch 7: softmax -> P (tf32)
    softmax_rows<<<NB * S, 256>>>(scp, gf + OP);

    // launch 8: O = P@VT^T (fp32), batched, K = S
    dim3 g_o(D / 128, S / 128, NB);
    mma_gemm<<<g_o, thr, SMEM_DYN>>>(gf + OP, gf + OVT,
                                     out, S, S, S, D, SSZ, SD, SD, 1.f);
}

// round 12
// speedup vs baseline: 1.1620x; 1.1620x over previous
#include <cuda_runtime.h>
#include <cuda_bf16.h>
#include <cstdint>

// ============================================================================
// SelfAttention, mma.sync bf16x3-split, cp.async 3-stage pipelined GEMMs.
// R12 = R9 (best: 958.9us) with the GEMM mainloop untouched, plus:
//   - all 4 fp32->bf16 hi/lo split converters merged into ONE launch
//   - vectorized softmax (float4 loads, 16B bf16-plane stores)
// ============================================================================

constexpr int S = 2048, D = 1024, NB = 4;
constexpr long SD  = (long)S * D;
constexpr long SSZ = (long)S * S;
constexpr long NX = (long)NB * S * D;
constexpr long NW = (long)D * D;
constexpr long NP = (long)NB * S * S;

// hi-plane layout: [x | Wq | Wk | Wv] is linear so one converter can map
// global idx -> same offset in both planes.
constexpr long OXH = 0,        OXL = NX;
constexpr long OWQH = 2*NX,    OWQL = OWQH+NW, OWKH = OWQH+2*NW, OWKL = OWQH+3*NW,
               OWVH = OWQH+4*NW, OWVL = OWQH+5*NW;
constexpr long OQH = 2*NX+6*NW, OQL = OQH+NX, OKH = OQH+2*NX, OKL = OQH+3*NX,
               OVTH = OQH+4*NX, OVTL = OQH+5*NX;
constexpr long OPH = OQH+6*NX,  OPL = OPH+NP;
constexpr long NBF = OPL + NP;

__device__ __align__(128) __nv_bfloat16 g_bf[NBF];
__device__ float g_sc[NP];

constexpr int STAGE  = 64 * 1024;          // AH|AL|BH|BL x 16KB
constexpr int OFF_AH = 0, OFF_AL = 16384, OFF_BH = 32768, OFF_BL = 49152;
constexpr int NSTG   = 3;
constexpr int SMEM_DYN = NSTG * STAGE + 1024;

#define SWZ(o) ((o) ^ (((o) >> 3) & 0x70))

// ---------------------------------------------------------------- helpers
__device__ __forceinline__ uint32_t smem_u32(const void* p) {
    uint32_t a;
    asm("{ .reg .u64 t; cvta.to.shared.u64 t, %1; cvt.u32.u64 %0, t; }"
        : "=r"(a) : "l"(p));
    return a;
}
__device__ __forceinline__ void ldsm4(uint32_t* r, uint32_t addr) {
    asm volatile("ldmatrix.sync.aligned.m8n8.x4.shared.b16 {%0,%1,%2,%3}, [%4];"
                 : "=r"(r[0]), "=r"(r[1]), "=r"(r[2]), "=r"(r[3]) : "r"(addr));
}
__device__ __forceinline__ void mma16816(float* d, const uint32_t* a,
                                         const uint32_t* b) {
    asm volatile(
        "mma.sync.aligned.m16n8k16.row.col.f32.bf16.bf16.f32 "
        "{%0,%1,%2,%3}, {%4,%5,%6,%7}, {%8,%9}, {%0,%1,%2,%3};"
        : "+f"(d[0]), "+f"(d[1]), "+f"(d[2]), "+f"(d[3])
        : "r"(a[0]), "r"(a[1]), "r"(a[2]), "r"(a[3]), "r"(b[0]), "r"(b[1]));
}
#define CPA16(dst, src) \
    asm volatile("cp.async.cg.shared.global [%0], [%1], 16;" \
                 :: "r"(dst), "l"(src) : "memory")
#define CP_COMMIT() asm volatile("cp.async.commit_group;" ::: "memory")

__device__ __forceinline__ void split2(float v0, float v1,
                                       uint32_t& h, uint32_t& l) {
    __nv_bfloat16 h0 = __float2bfloat16_rn(v0), h1 = __float2bfloat16_rn(v1);
    __nv_bfloat162 hh(h0, h1);
    __nv_bfloat162 ll(__float2bfloat16_rn(v0 - __bfloat162float(h0)),
                      __float2bfloat16_rn(v1 - __bfloat162float(h1)));
    h = *reinterpret_cast<uint32_t*>(&hh);
    l = *reinterpret_cast<uint32_t*>(&ll);
}

// ---------------------------------------------------------------- merged split
// One launch covers x, Wq, Wk, Wv. Planes are linear, so out offset == idx.
__global__ void __launch_bounds__(256)
split_all(const float* __restrict__ x, const float* __restrict__ wq,
          const float* __restrict__ wk, const float* __restrict__ wv)
{
    const long i = ((long)blockIdx.x * 256 + threadIdx.x) * 4;
    const long total = NX + 3 * NW;
    if (i >= total) return;
    const float* src;
    long loc = i;
    if (i < NX)               { src = x; }
    else if (i < NX + NW)     { src = wq; loc = i - NX; }
    else if (i < NX + 2 * NW) { src = wk; loc = i - NX - NW; }
    else                      { src = wv; loc = i - NX - 2 * NW; }
    float4 v = *reinterpret_cast<const float4*>(src + loc);
    uint2 h, l;
    split2(v.x, v.y, h.x, l.x);
    split2(v.z, v.w, h.y, l.y);
    *reinterpret_cast<uint2*>(&g_bf[OXH] + i) = h;   // hi plane at idx
    *reinterpret_cast<uint2*>(&g_bf[OXL] + i) = l;   // lo plane at idx + NX...
}
// NOTE on lo plane: layout is [xH|WqH|WkH|WvH | ... ] hi block then per-array
// lo blocks are NOT contiguous in R9's layout; see static_assert below.
static_assert(OXL == NX && OWQL == OWQH + NW && OWKL == OWKH + NW &&
              OWVL == OWVH + NW, "layout");

// The simple "+NX" trick is only valid for x. Correct lo offsets per region:
__global__ void __launch_bounds__(256)
split_all_fix(const float* __restrict__ x, const float* __restrict__ wq,
              const float* __restrict__ wk, const float* __restrict__ wv)
{
    const long i = ((long)blockIdx.x * 256 + threadIdx.x) * 4;
    const long total = NX + 3 * NW;
    if (i >= total) return;
    const float* src;
    long loc = i, oh, ol;
    if (i < NX)               { src = x;  oh = OXH + i;            ol = OXL + i; }
    else if (i < NX + NW)     { src = wq; loc = i - NX;
                                oh = OWQH + loc;                   ol = OWQL + loc; }
    else if (i < NX + 2 * NW) { src = wk; loc = i - NX - NW;
                                oh = OWKH + loc;                   ol = OWKL + loc; }
    else                      { src = wv; loc = i - NX - 2 * NW;
                                oh = OWVH + loc;                   ol = OWVL + loc; }
    float4 v = *reinterpret_cast<const float4*>(src + loc);
    uint2 h, l;
    split2(v.x, v.y, h.x, l.x);
    split2(v.z, v.w, h.y, l.y);
    *reinterpret_cast<uint2*>(&g_bf[0] + oh) = h;
    *reinterpret_cast<uint2*>(&g_bf[0] + ol) = l;
}

// ---------------------------------------------------------------- mainloop
// (byte-identical logic to R9) 512 thr, 16 warps (4m x 4n), warp 32x32,
// CTA 128x128, K-chunk 64, 3 stages. Pointers pre-offset. acc[32].
__device__ __forceinline__ void gemm_mainloop(
    const __nv_bfloat16* __restrict__ gAh, const __nv_bfloat16* __restrict__ gAl,
    const __nv_bfloat16* __restrict__ gBh, const __nv_bfloat16* __restrict__ gBl,
    int lda, int ldb, int K, uint32_t abase, float* acc)
{
    const int tid = threadIdx.x, lane = tid & 31, wid = tid >> 5;

    const int r0 = tid >> 3, s0 = tid & 7;
    const uint32_t w0 = SWZ((uint32_t)r0 * 128 + s0 * 16);
    const uint32_t w1 = SWZ((uint32_t)(r0 + 64) * 128 + s0 * 16);
    const __nv_bfloat16* ga[8] = {
        gAh + (long)r0 * lda + s0 * 8,
        gAh + (long)(r0 + 64) * lda + s0 * 8,
        gAl + (long)r0 * lda + s0 * 8,
        gAl + (long)(r0 + 64) * lda + s0 * 8,
        gBh + (long)r0 * ldb + s0 * 8,
        gBh + (long)(r0 + 64) * ldb + s0 * 8,
        gBl + (long)r0 * ldb + s0 * 8,
        gBl + (long)(r0 + 64) * ldb + s0 * 8 };
    const uint32_t soff[8] = { OFF_AH + w0, OFF_AH + w1, OFF_AL + w0, OFF_AL + w1,
                               OFF_BH + w0, OFF_BH + w1, OFF_BL + w0, OFF_BL + w1 };

    const int mw = (wid >> 2) * 32, nw = (wid & 3) * 32;
    uint32_t a_row[2], a_swz[2];
#pragma unroll
    for (int i = 0; i < 2; i++) {
        uint32_t rb = (uint32_t)(mw + 16 * i + (lane & 15)) * 128;
        a_row[i] = rb; a_swz[i] = (rb >> 3) & 0x70;
    }
    const uint32_t a_kl = (uint32_t)((lane >> 4) << 4);
    uint32_t b_row[2], b_swz[2];
#pragma unroll
    for (int p = 0; p < 2; p++) {
        uint32_t rb = (uint32_t)(nw + 16 * p + (lane & 7) + ((lane & 16) >> 1)) * 128;
        b_row[p] = rb; b_swz[p] = (rb >> 3) & 0x70;
    }
    const uint32_t b_kl = (uint32_t)((lane & 8) << 1);

    const int nch = K >> 6;

#define ISSUE(ch) do {                                                        \
        const uint32_t _sb = abase + (uint32_t)((ch) % NSTG) * STAGE;         \
        const long _k = (long)(ch) * 64;                                      \
        _Pragma("unroll")                                                     \
        for (int q = 0; q < 8; q++) CPA16(_sb + soff[q], ga[q] + _k);         \
        CP_COMMIT();                                                          \
    } while (0)

    ISSUE(0);
    ISSUE(1);

    for (int ch = 0; ch < nch; ch++) {
        if (ch + 1 < nch)
            asm volatile("cp.async.wait_group 1;" ::: "memory");
        else
            asm volatile("cp.async.wait_group 0;" ::: "memory");
        __syncthreads();
        if (ch + 2 < nch) ISSUE(ch + 2);

        const uint32_t sb = abase + (uint32_t)(ch % NSTG) * STAGE;
#pragma unroll
        for (int ks = 0; ks < 4; ks++) {
            const uint32_t KB = ks * 32;
            uint32_t af[2][4], bh[8], bl[8];
#pragma unroll
            for (int i = 0; i < 2; i++)
                ldsm4(af[i], sb + OFF_AH + a_row[i] + ((KB + a_kl) ^ a_swz[i]));
#pragma unroll
            for (int p = 0; p < 2; p++) {
                const uint32_t ko = KB + b_kl;
                ldsm4(&bh[4 * p], sb + OFF_BH + b_row[p] + (ko ^ b_swz[p]));
                ldsm4(&bl[4 * p], sb + OFF_BL + b_row[p] + (ko ^ b_swz[p]));
            }
#pragma unroll
            for (int i = 0; i < 2; i++)
#pragma unroll
                for (int j = 0; j < 4; j++)
                    mma16816(acc + (i * 4 + j) * 4, af[i], &bh[j * 2]);  // hi*hi
#pragma unroll
            for (int i = 0; i < 2; i++)
#pragma unroll
                for (int j = 0; j < 4; j++)
                    mma16816(acc + (i * 4 + j) * 4, af[i], &bl[j * 2]);  // hi*lo
#pragma unroll
            for (int i = 0; i < 2; i++)
                ldsm4(af[i], sb + OFF_AL + a_row[i] + ((KB + a_kl) ^ a_swz[i]));
#pragma unroll
            for (int i = 0; i < 2; i++)
#pragma unroll
                for (int j = 0; j < 4; j++)
                    mma16816(acc + (i * 4 + j) * 4, af[i], &bh[j * 2]);  // lo*hi
        }
    }
#undef ISSUE
}

// ---------------------------------------------------------------- fused QKV
__global__ void __launch_bounds__(512, 1)
mma_qkv(const float* __restrict__ bq, const float* __restrict__ bk,
        const float* __restrict__ bv)
{
    const int z = blockIdx.z;
    const long row0 = (long)blockIdx.y * 128, col0 = (long)blockIdx.x * 128;

    extern __shared__ char smem_raw[];
    const uint32_t rawb  = smem_u32(smem_raw);
    const uint32_t abase = (rawb + 1023) & ~1023u;
    char* smem = smem_raw + (abase - rawb);

    const __nv_bfloat16* Wh = &g_bf[z == 0 ? OWQH : z == 1 ? OWKH : OWVH];
    const __nv_bfloat16* Wl = &g_bf[z == 0 ? OWQL : z == 1 ? OWKL : OWVL];
    const float* bias = z == 0 ? bq : z == 1 ? bk : bv;

    float acc[32];
#pragma unroll
    for (int i = 0; i < 32; i++) acc[i] = 0.f;

    gemm_mainloop(&g_bf[OXH] + row0 * D, &g_bf[OXL] + row0 * D,
                  Wh + col0 * D, Wl + col0 * D, D, D, D, abase, acc);

    const int tid = threadIdx.x, lane = tid & 31, wid = tid >> 5;
    const int mw = (wid >> 2) * 32, nw = (wid & 3) * 32;
    const int qr = lane >> 2, qc = lane & 3;

    if (z < 2) {
        __nv_bfloat16* Ch = &g_bf[z == 0 ? OQH : OKH];
        __nv_bfloat16* Cl = &g_bf[z == 0 ? OQL : OKL];
#pragma unroll
        for (int i = 0; i < 2; i++)
#pragma unroll
            for (int j = 0; j < 4; j++) {
                const float* d = acc + (i * 4 + j) * 4;
#pragma unroll
                for (int h = 0; h < 2; h++) {
                    const long r = row0 + mw + 16 * i + qr + 8 * h;
                    const long c = col0 + nw + 8 * j + 2 * qc;
                    float v0 = d[2 * h] + bias[c], v1 = d[2 * h + 1] + bias[c + 1];
                    uint32_t hh, ll;
                    split2(v0, v1, hh, ll);
                    *reinterpret_cast<uint32_t*>(&Ch[r * D + c]) = hh;
                    *reinterpret_cast<uint32_t*>(&Cl[r * D + c]) = ll;
                }
            }
    } else {
        const long b = row0 >> 11, rloc = row0 & (S - 1);
        __nv_bfloat16* Ch = &g_bf[OVTH] + b * SD;
        __nv_bfloat16* Cl = &g_bf[OVTL] + b * SD;
        __syncthreads();
        __nv_bfloat16* sh = reinterpret_cast<__nv_bfloat16*>(smem);
        __nv_bfloat16* sl = sh + 128 * 136;
#pragma unroll
        for (int i = 0; i < 2; i++)
#pragma unroll
            for (int j = 0; j < 4; j++) {
                const float* d = acc + (i * 4 + j) * 4;
#pragma unroll
                for (int h = 0; h < 2; h++) {
                    const int rl = mw + 16 * i + qr + 8 * h;
                    const int cl = nw + 8 * j + 2 * qc;
                    float v0 = d[2 * h] + bias[col0 + cl];
                    float v1 = d[2 * h + 1] + bias[col0 + cl + 1];
                    __nv_bfloat16 h0 = __float2bfloat16_rn(v0);
                    __nv_bfloat16 h1 = __float2bfloat16_rn(v1);
                    sh[cl * 136 + rl]       = h0;
                    sh[(cl + 1) * 136 + rl] = h1;
                    sl[cl * 136 + rl] =
                        __float2bfloat16_rn(v0 - __bfloat162float(h0));
                    sl[(cl + 1) * 136 + rl] =
                        __float2bfloat16_rn(v1 - __bfloat162float(h1));
                }
            }
        __syncthreads();
        const int c = tid >> 2, seg = tid & 3;
        const __nv_bfloat16* srh = sh + c * 136 + seg * 32;
        const __nv_bfloat16* srl = sl + c * 136 + seg * 32;
        __nv_bfloat16* dsh = Ch + (col0 + c) * (long)S + rloc + seg * 32;
        __nv_bfloat16* dsl = Cl + (col0 + c) * (long)S + rloc + seg * 32;
#pragma unroll
        for (int q = 0; q < 4; q++) {
            *reinterpret_cast<uint4*>(dsh + q * 8) =
                *reinterpret_cast<const uint4*>(srh + q * 8);
            *reinterpret_cast<uint4*>(dsl + q * 8) =
                *reinterpret_cast<const uint4*>(srl + q * 8);
        }
    }
}

// ---------------------------------------------------------------- generic GEMM
__global__ void __launch_bounds__(512, 1)
mma_gemm(const __nv_bfloat16* __restrict__ Ah, const __nv_bfloat16* __restrict__ Al,
         const __nv_bfloat16* __restrict__ Bh, const __nv_bfloat16* __restrict__ Bl,
         float* __restrict__ Cf, int K, int lda, int ldb, int ldc,
         long sA, long sB, long sC, float scale)
{
    const long zb = blockIdx.z;
    const long row0 = (long)blockIdx.y * 128, col0 = (long)blockIdx.x * 128;

    extern __shared__ char smem_raw[];
    const uint32_t rawb  = smem_u32(smem_raw);
    const uint32_t abase = (rawb + 1023) & ~1023u;

    float acc[32];
#pragma unroll
    for (int i = 0; i < 32; i++) acc[i] = 0.f;

    gemm_mainloop(Ah + sA * zb + row0 * (long)lda, Al + sA * zb + row0 * (long)lda,
                  Bh + sB * zb + col0 * (long)ldb, Bl + sB * zb + col0 * (long)ldb,
                  lda, ldb, K, abase, acc);

    float* Cp = Cf + sC * zb;
    const int tid = threadIdx.x, lane = tid & 31, wid = tid >> 5;
    const int mw = (wid >> 2) * 32, nw = (wid & 3) * 32;
    const int qr = lane >> 2, qc = lane & 3;
#pragma unroll
    for (int i = 0; i < 2; i++)
#pragma unroll
        for (int j = 0; j < 4; j++) {
            const float* d = acc + (i * 4 + j) * 4;
#pragma unroll
            for (int h = 0; h < 2; h++) {
                const long r = row0 + mw + 16 * i + qr + 8 * h;
                const long c = col0 + nw + 8 * j + 2 * qc;
                *reinterpret_cast<float2*>(&Cp[r * (long)ldc + c]) =
                    make_float2(d[2 * h] * scale, d[2 * h + 1] * scale);
            }
        }
}

// ---------------------------------------------------------------- softmax
// Per-thread elements contiguous: v[0..7] = row[t*8 .. t*8+7], float4 loads,
// uint4 (8 x bf16) stores per plane.
__global__ void __launch_bounds__(256)
softmax_rows(const float* __restrict__ sc, __nv_bfloat16* __restrict__ ph,
             __nv_bfloat16* __restrict__ pl)
{
    const long ro = (long)blockIdx.x * 2048;
    const float* p = sc + ro;
    __shared__ float red[8];
    const int t = threadIdx.x, lane = t & 31, w = t >> 5;

    float v[8];
    *reinterpret_cast<float4*>(v)     = *reinterpret_cast<const float4*>(p + t * 8);
    *reinterpret_cast<float4*>(v + 4) = *reinterpret_cast<const float4*>(p + t * 8 + 4);

    float m = v[0];
#pragma unroll
    for (int i = 1; i < 8; i++) m = fmaxf(m, v[i]);
#pragma unroll
    for (int o = 16; o > 0; o >>= 1)
        m = fmaxf(m, __shfl_xor_sync(0xffffffffu, m, o));
    if (lane == 0) red[w] = m;
    __syncthreads();
    m = red[lane & 7];
#pragma unroll
    for (int o = 4; o > 0; o >>= 1)
        m = fmaxf(m, __shfl_xor_sync(0xffffffffu, m, o));

    float sum = 0.f;
#pragma unroll
    for (int i = 0; i < 8; i++) { v[i] = __expf(v[i] - m); sum += v[i]; }
#pragma unroll
    for (int o = 16; o > 0; o >>= 1)
        sum += __shfl_xor_sync(0xffffffffu, sum, o);
    __syncthreads();
    if (lane == 0) red[w] = sum;
    __syncthreads();
    sum = red[lane & 7];
#pragma unroll
    for (int o = 4; o > 0; o >>= 1)
        sum += __shfl_xor_sync(0xffffffffu, sum, o);
    const float inv = 1.f / sum;

    uint32_t hh[4], ll[4];
#pragma unroll
    for (int i = 0; i < 4; i++) {
        float p0 = v[2 * i] * inv, p1 = v[2 * i + 1] * inv;
        split2(p0, p1, hh[i], ll[i]);
    }
    *reinterpret_cast<uint4*>(ph + ro + t * 8) =
        make_uint4(hh[0], hh[1], hh[2], hh[3]);
    *reinterpret_cast<uint4*>(pl + ro + t * 8) =
        make_uint4(ll[0], ll[1], ll[2], ll[3]);
}

// ---------------------------------------------------------------- launch
extern "C" void kernel_launch(void* const* d_in, const int* in_sizes, int n_in,
                              void* d_out, int out_size)
{
    const float* x  = (const float*)d_in[0];
    const float* Wq = (const float*)d_in[1];
    const float* bq = (const float*)d_in[2];
    const float* Wk = (const float*)d_in[3];
    const float* bk = (const float*)d_in[4];
    const float* Wv = (const float*)d_in[5];
    const float* bv = (const float*)d_in[6];
    float* out = (float*)d_out;

    __nv_bfloat16* bf; float* scp;
    cudaGetSymbolAddress((void**)&bf, g_bf);
    cudaGetSymbolAddress((void**)&scp, g_sc);

    cudaFuncSetAttribute(mma_qkv, cudaFuncAttributeMaxDynamicSharedMemorySize,
                         SMEM_DYN);
    cudaFuncSetAttribute(mma_gemm, cudaFuncAttributeMaxDynamicSharedMemorySize,
                         SMEM_DYN);
    dim3 thr(512);

    // launch 1: merged split of x, Wq, Wk, Wv
    const long tot = NX + 3 * NW;
    split_all_fix<<<(int)((tot / 4 + 255) / 256), 256>>>(x, Wq, Wk, Wv);

    // launch 2: fused Q/K/VT projections
    dim3 g_qkv(D / 128, (NB * S) / 128, 3);
    mma_qkv<<<g_qkv, thr, SMEM_DYN>>>(bq, bk, bv);

    // launch 3: Sc = Q@K^T / 32 (fp32), batched
    dim3 g_sc(S / 128, S / 128, NB);
    mma_gemm<<<g_sc, thr, SMEM_DYN>>>(bf+OQH, bf+OQL, bf+OKH, bf+OKL,
                                      scp, D, D, D, S, SD, SD, SSZ, 0.03125f);

    // launch 4: softmax -> P hi/lo
    softmax_rows<<<NB * S, 256>>>(scp, bf + OPH, bf + OPL);

    // launch 5: O = P@VT^T (fp32), batched, K = S
    dim3 g_o(D / 128, S / 128, NB);
    mma_gemm<<<g_o, thr, SMEM_DYN>>>(bf+OPH, bf+OPL, bf+OVTH, bf+OVTL,
                                     out, S, S, S, D, SSZ, SD, SD, 1.f);
}